// round 6
// baseline (speedup 1.0000x reference)
#include <cuda_runtime.h>

#define THREADS 512
#define RPB 16
#define LD_H 264
#define LD_W2 260

// smem layout (float offsets)
#define OFF_W0T 0
#define OFF_W2S 8192
#define OFF_B0  16512
#define OFF_B1  16768
#define OFF_B2  17024
#define OFF_Y   17056
#define OFF_K   17568
#define OFF_Z   20640
#define OFF_H0  21152
#define OFF_H1  25376
#define OFF_W1B 29600
#define SMEM_BYTES ((29600 + 3 * 8192) * 4)

typedef unsigned long long u64;

__constant__ float c_A[6][5] = {
  {0.f,0.f,0.f,0.f,0.f},
  {0.161f,0.f,0.f,0.f,0.f},
  {-0.008480655492356989f,0.335480655492357f,0.f,0.f,0.f},
  {2.8971530571054935f,-6.359448489975075f,4.3622954328695815f,0.f,0.f},
  {5.325864828439257f,-11.748883564062828f,7.4955393428898365f,-0.09249506636175525f,0.f},
  {5.86145544294642f,-12.92096931784711f,8.159367898576159f,-0.071584973281401f,-0.028269050394068383f}};
__constant__ float c_B[6] = {
  0.09646076681806523f,0.01f,0.4798896504144996f,
  1.379008574103742f,-3.290069515436081f,2.324710524099774f};

__device__ float g_w1t[256 * 256]; // g_w1t[k*256+o] = W1[o*256+k]

__device__ __forceinline__ void cp16(float* dst, const float* src) {
  unsigned d = (unsigned)__cvta_generic_to_shared(dst);
  asm volatile("cp.async.ca.shared.global [%0], [%1], 16;" :: "r"(d), "l"(src));
}
__device__ __forceinline__ void cpcommit(){ asm volatile("cp.async.commit_group;"); }
template<int N> __device__ __forceinline__ void cpwait(){ asm volatile("cp.async.wait_group %0;"::"n"(N)); }

__device__ __forceinline__ u64 dup2(float a) {
  u64 r; asm("mov.b64 %0, {%1, %1};" : "=l"(r) : "f"(a)); return r;
}
__device__ __forceinline__ float2 unpk(u64 v) {
  float2 r; asm("mov.b64 {%0, %1}, %2;" : "=f"(r.x), "=f"(r.y) : "l"(v)); return r;
}
__device__ __forceinline__ void ffma2(u64& acc, u64 a, u64 b) {
  asm("fma.rn.f32x2 %0, %1, %2, %0;" : "+l"(acc) : "l"(a), "l"(b));
}

// MUFU softplus
__device__ __forceinline__ float softplusf(float x) {
  float e, l;
  asm("ex2.approx.f32 %0, %1;" : "=f"(e) : "f"(x * 1.4426950408889634f));
  asm("lg2.approx.f32 %0, %1;" : "=f"(l) : "f"(1.0f + e));
  float r = l * 0.69314718055994531f;
  return (x > 15.0f) ? x : r;
}

__device__ __forceinline__ float f4get(const float4& v, int j) {
  return (j==0)?v.x:(j==1)?v.y:(j==2)?v.z:v.w;
}

__global__ void w1t_kernel(const float* __restrict__ W1) {
  __shared__ float tile[32][33];
  int k = blockIdx.x * 32 + threadIdx.x;
#pragma unroll
  for (int j = 0; j < 32; j += 8) {
    int o = blockIdx.y * 32 + threadIdx.y + j;
    tile[threadIdx.y + j][threadIdx.x] = W1[o * 256 + k];
  }
  __syncthreads();
  int o2 = blockIdx.y * 32 + threadIdx.x;
#pragma unroll
  for (int j = 0; j < 32; j += 8) {
    int k2 = blockIdx.x * 32 + threadIdx.y + j;
    g_w1t[k2 * 256 + o2] = tile[threadIdx.x][threadIdx.y + j];
  }
}

__global__ void __launch_bounds__(THREADS, 1)
ode_kernel(const float* __restrict__ ts, const float* __restrict__ y0,
           const float* __restrict__ W0, const float* __restrict__ b0,
           const float* __restrict__ b1, const float* __restrict__ W2,
           const float* __restrict__ b2, float* __restrict__ out, int T, int B) {
  extern __shared__ float sm[];
  float *w0t=sm+OFF_W0T, *w2s=sm+OFF_W2S, *b0s=sm+OFF_B0, *b1s=sm+OFF_B1,
        *b2s=sm+OFF_B2, *ysm=sm+OFF_Y, *ksm=sm+OFF_K, *zb=sm+OFF_Z,
        *h0=sm+OFF_H0, *h1=sm+OFF_H1, *w1b=sm+OFF_W1B;
  const int tid = threadIdx.x;
  const int rbase = blockIdx.x * RPB;

  for (int idx = tid; idx < 256*32; idx += THREADS) {
    int o = idx >> 5, k = idx & 31;
    w0t[k*256 + o] = W0[idx];
  }
  for (int idx = tid; idx < 32*256; idx += THREADS) {
    int d = idx >> 8, k = idx & 255;
    w2s[d*LD_W2 + k] = W2[idx];
  }
  for (int i = tid; i < 256; i += THREADS) { b0s[i]=b0[i]; b1s[i]=b1[i]; }
  if (tid < 32) b2s[tid] = b2[tid];
  for (int idx = tid; idx < RPB*32; idx += THREADS) {
    float v = y0[rbase*32 + idx];
    ysm[idx] = v;
    out[rbase*32 + idx] = v;
  }
  __syncthreads();

  // layers 0/1: 2 rows x 4 cols per thread (8 row-groups x 64 col-groups)
  const int cg = tid & 63, rg = tid >> 6;
  const int c0 = cg*4, r0 = rg*2;
  // layer 2: 1 output per thread
  const int d2 = tid & 31, rr = tid >> 5;

  for (int s = 0; s < T-1; ++s) {
    const float h = (ts[s+1] - ts[s]) * 0.5f;  // NSUB=2
    for (int sub = 0; sub < 2; ++sub) {
      for (int st = 0; st < 6; ++st) {
        // prefetch W1 tiles 0,1
#pragma unroll
        for (int q = 0; q < 4; ++q) {
          int e = (q*THREADS + tid) * 4;
          cp16(w1b + e, g_w1t + e);
        }
        cpcommit();
#pragma unroll
        for (int q = 0; q < 4; ++q) {
          int e = (q*THREADS + tid) * 4;
          cp16(w1b + 8192 + e, g_w1t + 8192 + e);
        }
        cpcommit();

        // z = y + h * sum A[st][j] k_j  (1 elem/thread)
        {
          float acc = ysm[tid];
          for (int j = 0; j < st; ++j)
            acc = fmaf(h * c_A[st][j], ksm[j*512 + tid], acc);
          zb[tid] = acc;
        }
        __syncthreads();

        // layer 0: h0 = softplus(z @ W0^T + b0), K=32
        u64 a0[2][2];
        {
          u64 bp0 = *(const u64*)(b0s + c0);
          u64 bp1 = *(const u64*)(b0s + c0 + 2);
#pragma unroll
          for (int i=0;i<2;i++) { a0[i][0]=bp0; a0[i][1]=bp1; }
        }
#pragma unroll
        for (int kk = 0; kk < 32; kk += 4) {
          float4 av[2]; ulonglong2 wv[4];
#pragma unroll
          for (int i=0;i<2;i++) av[i] = *(const float4*)(zb + (r0+i)*32 + kk);
#pragma unroll
          for (int t=0;t<4;t++) wv[t] = *(const ulonglong2*)(w0t + (kk+t)*256 + c0);
#pragma unroll
          for (int t=0;t<4;t++)
#pragma unroll
            for (int i=0;i<2;i++) {
              u64 ad = dup2(f4get(av[i], t));
              ffma2(a0[i][0], ad, wv[t].x);
              ffma2(a0[i][1], ad, wv[t].y);
            }
        }
#pragma unroll
        for (int i=0;i<2;i++) {
          float2 u0 = unpk(a0[i][0]), u1 = unpk(a0[i][1]);
          float4 o4;
          o4.x = softplusf(u0.x); o4.y = softplusf(u0.y);
          o4.z = softplusf(u1.x); o4.w = softplusf(u1.y);
          *(float4*)(h0 + (r0+i)*LD_H + c0) = o4;
        }

        // layer 1: K=256, triple-buffered W1 stream
        u64 a1[2][2];
        {
          u64 bp0 = *(const u64*)(b1s + c0);
          u64 bp1 = *(const u64*)(b1s + c0 + 2);
#pragma unroll
          for (int i=0;i<2;i++) { a1[i][0]=bp0; a1[i][1]=bp1; }
        }
        for (int kt = 0; kt < 8; ++kt) {
          if (kt < 7) cpwait<1>(); else cpwait<0>();
          __syncthreads();  // tile kt landed; fences h0 on kt==0
          if (kt < 6) {
            const float* src = g_w1t + (kt+2)*8192;
            float* dst = w1b + ((kt+2)%3)*8192;
#pragma unroll
            for (int q = 0; q < 4; ++q) {
              int e = (q*THREADS + tid) * 4;
              cp16(dst + e, src + e);
            }
            cpcommit();
          }
          const float* wb = w1b + (kt%3)*8192;
          const int kb = kt*32;
#pragma unroll
          for (int kk = 0; kk < 32; kk += 4) {
            float4 av[2]; ulonglong2 wv[4];
#pragma unroll
            for (int i=0;i<2;i++) av[i] = *(const float4*)(h0 + (r0+i)*LD_H + kb + kk);
#pragma unroll
            for (int t=0;t<4;t++) wv[t] = *(const ulonglong2*)(wb + (kk+t)*256 + c0);
#pragma unroll
            for (int t=0;t<4;t++)
#pragma unroll
              for (int i=0;i<2;i++) {
                u64 ad = dup2(f4get(av[i], t));
                ffma2(a1[i][0], ad, wv[t].x);
                ffma2(a1[i][1], ad, wv[t].y);
              }
          }
        }
#pragma unroll
        for (int i=0;i<2;i++) {
          float2 u0 = unpk(a1[i][0]), u1 = unpk(a1[i][1]);
          float4 o4;
          o4.x = softplusf(u0.x); o4.y = softplusf(u0.y);
          o4.z = softplusf(u1.x); o4.w = softplusf(u1.y);
          *(float4*)(h1 + (r0+i)*LD_H + c0) = o4;
        }
        __syncthreads();

        // layer 2: 1 output/thread, 4 split accumulators (u64) for ILP
        {
          u64 s0 = 0ULL, s1 = 0ULL, s2 = 0ULL, s3 = 0ULL;
#pragma unroll 4
          for (int kk = 0; kk < 256; kk += 8) {
            ulonglong2 wv0 = *(const ulonglong2*)(w2s + d2*LD_W2 + kk);
            ulonglong2 wv1 = *(const ulonglong2*)(w2s + d2*LD_W2 + kk + 4);
            ulonglong2 ua0 = *(const ulonglong2*)(h1 + rr*LD_H + kk);
            ulonglong2 ua1 = *(const ulonglong2*)(h1 + rr*LD_H + kk + 4);
            ffma2(s0, ua0.x, wv0.x); ffma2(s1, ua0.y, wv0.y);
            ffma2(s2, ua1.x, wv1.x); ffma2(s3, ua1.y, wv1.y);
          }
          float2 f0 = unpk(s0), f1 = unpk(s1), f2 = unpk(s2), f3 = unpk(s3);
          ksm[st*512 + rr*32 + d2] =
            ((f0.x + f0.y) + (f1.x + f1.y)) + ((f2.x + f2.y) + (f3.x + f3.y)) + b2s[d2];
        }
        __syncthreads();
      } // stages

      // y += h * (B . k); save at end of interval
      {
        float acc = ysm[tid];
#pragma unroll
        for (int j = 0; j < 6; ++j)
          acc = fmaf(h * c_B[j], ksm[j*512 + tid], acc);
        ysm[tid] = acc;
        if (sub == 1)
          out[(size_t)(s+1)*B*32 + rbase*32 + tid] = acc;
      }
      __syncthreads();
    } // sub
  } // intervals
}

extern "C" void kernel_launch(void* const* d_in, const int* in_sizes, int n_in,
                              void* d_out, int out_size) {
  const float* ts = (const float*)d_in[0];
  const float* y0 = (const float*)d_in[1];
  const float* W0 = (const float*)d_in[2];
  const float* b0 = (const float*)d_in[3];
  const float* W1 = (const float*)d_in[4];
  const float* b1 = (const float*)d_in[5];
  const float* W2 = (const float*)d_in[6];
  const float* b2 = (const float*)d_in[7];
  float* out = (float*)d_out;
  int T = in_sizes[0];
  int B = in_sizes[1] / 32;

  w1t_kernel<<<dim3(8, 8), dim3(32, 8)>>>(W1);

  static int smem_set = 0;
  if (!smem_set) {
    cudaFuncSetAttribute(ode_kernel, cudaFuncAttributeMaxDynamicSharedMemorySize, SMEM_BYTES);
    smem_set = 1;
  }
  ode_kernel<<<B / RPB, THREADS, SMEM_BYTES>>>(ts, y0, W0, b0, b1, W2, b2, out, T, B);
}

// round 7
// speedup vs baseline: 1.0007x; 1.0007x over previous
#include <cuda_runtime.h>

#define THREADS 512
#define RPB 16
#define LD_H 264
#define LD_W2 260

// smem layout (float offsets)
#define OFF_W0T 0
#define OFF_W2S 8192
#define OFF_B0  16512
#define OFF_B1  16768
#define OFF_B2  17024
#define OFF_Y   17056
#define OFF_K   17568
#define OFF_Z   20640
#define OFF_H0  21152
#define OFF_H1  25376
#define OFF_W1B 29600
#define SMEM_BYTES ((29600 + 3 * 8192) * 4)

typedef unsigned long long u64;

__constant__ float c_A[6][5] = {
  {0.f,0.f,0.f,0.f,0.f},
  {0.161f,0.f,0.f,0.f,0.f},
  {-0.008480655492356989f,0.335480655492357f,0.f,0.f,0.f},
  {2.8971530571054935f,-6.359448489975075f,4.3622954328695815f,0.f,0.f},
  {5.325864828439257f,-11.748883564062828f,7.4955393428898365f,-0.09249506636175525f,0.f},
  {5.86145544294642f,-12.92096931784711f,8.159367898576159f,-0.071584973281401f,-0.028269050394068383f}};
__constant__ float c_B[6] = {
  0.09646076681806523f,0.01f,0.4798896504144996f,
  1.379008574103742f,-3.290069515436081f,2.324710524099774f};

__device__ float g_w1t[256 * 256]; // g_w1t[k*256+o] = W1[o*256+k]

__device__ __forceinline__ void cp16(float* dst, const float* src) {
  unsigned d = (unsigned)__cvta_generic_to_shared(dst);
  asm volatile("cp.async.ca.shared.global [%0], [%1], 16;" :: "r"(d), "l"(src));
}
__device__ __forceinline__ void cpcommit(){ asm volatile("cp.async.commit_group;"); }
template<int N> __device__ __forceinline__ void cpwait(){ asm volatile("cp.async.wait_group %0;"::"n"(N)); }

__device__ __forceinline__ u64 dup2(float a) {
  u64 r; asm("mov.b64 %0, {%1, %1};" : "=l"(r) : "f"(a)); return r;
}
__device__ __forceinline__ float2 unpk(u64 v) {
  float2 r; asm("mov.b64 {%0, %1}, %2;" : "=f"(r.x), "=f"(r.y) : "l"(v)); return r;
}
__device__ __forceinline__ void ffma2(u64& acc, u64 a, u64 b) {
  asm("fma.rn.f32x2 %0, %1, %2, %0;" : "+l"(acc) : "l"(a), "l"(b));
}

// MUFU softplus
__device__ __forceinline__ float softplusf(float x) {
  float e, l;
  asm("ex2.approx.f32 %0, %1;" : "=f"(e) : "f"(x * 1.4426950408889634f));
  asm("lg2.approx.f32 %0, %1;" : "=f"(l) : "f"(1.0f + e));
  float r = l * 0.69314718055994531f;
  return (x > 15.0f) ? x : r;
}

__device__ __forceinline__ float f4get(const float4& v, int j) {
  return (j==0)?v.x:(j==1)?v.y:(j==2)?v.z:v.w;
}

__global__ void w1t_kernel(const float* __restrict__ W1) {
  __shared__ float tile[32][33];
  int k = blockIdx.x * 32 + threadIdx.x;
#pragma unroll
  for (int j = 0; j < 32; j += 8) {
    int o = blockIdx.y * 32 + threadIdx.y + j;
    tile[threadIdx.y + j][threadIdx.x] = W1[o * 256 + k];
  }
  __syncthreads();
  int o2 = blockIdx.y * 32 + threadIdx.x;
#pragma unroll
  for (int j = 0; j < 32; j += 8) {
    int k2 = blockIdx.x * 32 + threadIdx.y + j;
    g_w1t[k2 * 256 + o2] = tile[threadIdx.x][threadIdx.y + j];
  }
}

__global__ void __launch_bounds__(THREADS, 1)
ode_kernel(const float* __restrict__ ts, const float* __restrict__ y0,
           const float* __restrict__ W0, const float* __restrict__ b0,
           const float* __restrict__ b1, const float* __restrict__ W2,
           const float* __restrict__ b2, float* __restrict__ out, int T, int B) {
  extern __shared__ float sm[];
  float *w0t=sm+OFF_W0T, *w2s=sm+OFF_W2S, *b0s=sm+OFF_B0, *b1s=sm+OFF_B1,
        *b2s=sm+OFF_B2, *ysm=sm+OFF_Y, *ksm=sm+OFF_K, *zb=sm+OFF_Z,
        *h0=sm+OFF_H0, *h1=sm+OFF_H1, *w1b=sm+OFF_W1B;
  const int tid = threadIdx.x;
  const int rbase = blockIdx.x * RPB;

  for (int idx = tid; idx < 256*32; idx += THREADS) {
    int o = idx >> 5, k = idx & 31;
    w0t[k*256 + o] = W0[idx];
  }
  for (int idx = tid; idx < 32*256; idx += THREADS) {
    int d = idx >> 8, k = idx & 255;
    w2s[d*LD_W2 + k] = W2[idx];
  }
  for (int i = tid; i < 256; i += THREADS) { b0s[i]=b0[i]; b1s[i]=b1[i]; }
  if (tid < 32) b2s[tid] = b2[tid];
  for (int idx = tid; idx < RPB*32; idx += THREADS) {
    float v = y0[rbase*32 + idx];
    ysm[idx] = v;
    out[rbase*32 + idx] = v;
  }
  __syncthreads();

  // layers 0/1: 2 rows x 4 cols per thread (8 row-groups x 64 col-groups)
  const int cg = tid & 63, rg = tid >> 6;
  const int c0 = cg*4, r0 = rg*2;
  // layer 2: 1 output per thread
  const int d2 = tid & 31, rr = tid >> 5;

  for (int s = 0; s < T-1; ++s) {
    const float h = (ts[s+1] - ts[s]) * 0.5f;  // NSUB=2
    for (int sub = 0; sub < 2; ++sub) {
      for (int st = 0; st < 6; ++st) {
        // prefetch W1 tiles 0,1
#pragma unroll
        for (int q = 0; q < 4; ++q) {
          int e = (q*THREADS + tid) * 4;
          cp16(w1b + e, g_w1t + e);
        }
        cpcommit();
#pragma unroll
        for (int q = 0; q < 4; ++q) {
          int e = (q*THREADS + tid) * 4;
          cp16(w1b + 8192 + e, g_w1t + 8192 + e);
        }
        cpcommit();

        // z = y + h * sum A[st][j] k_j  (1 elem/thread)
        {
          float acc = ysm[tid];
          for (int j = 0; j < st; ++j)
            acc = fmaf(h * c_A[st][j], ksm[j*512 + tid], acc);
          zb[tid] = acc;
        }
        __syncthreads();

        // layer 0: h0 = softplus(z @ W0^T + b0), K=32
        u64 a0[2][2];
        {
          u64 bp0 = *(const u64*)(b0s + c0);
          u64 bp1 = *(const u64*)(b0s + c0 + 2);
#pragma unroll
          for (int i=0;i<2;i++) { a0[i][0]=bp0; a0[i][1]=bp1; }
        }
#pragma unroll
        for (int kk = 0; kk < 32; kk += 4) {
          float4 av[2]; ulonglong2 wv[4];
#pragma unroll
          for (int i=0;i<2;i++) av[i] = *(const float4*)(zb + (r0+i)*32 + kk);
#pragma unroll
          for (int t=0;t<4;t++) wv[t] = *(const ulonglong2*)(w0t + (kk+t)*256 + c0);
#pragma unroll
          for (int t=0;t<4;t++)
#pragma unroll
            for (int i=0;i<2;i++) {
              u64 ad = dup2(f4get(av[i], t));
              ffma2(a0[i][0], ad, wv[t].x);
              ffma2(a0[i][1], ad, wv[t].y);
            }
        }
#pragma unroll
        for (int i=0;i<2;i++) {
          float2 u0 = unpk(a0[i][0]), u1 = unpk(a0[i][1]);
          float4 o4;
          o4.x = softplusf(u0.x); o4.y = softplusf(u0.y);
          o4.z = softplusf(u1.x); o4.w = softplusf(u1.y);
          *(float4*)(h0 + (r0+i)*LD_H + c0) = o4;
        }

        // layer 1: K=256, triple-buffered W1 stream
        u64 a1[2][2];
        {
          u64 bp0 = *(const u64*)(b1s + c0);
          u64 bp1 = *(const u64*)(b1s + c0 + 2);
#pragma unroll
          for (int i=0;i<2;i++) { a1[i][0]=bp0; a1[i][1]=bp1; }
        }
        for (int kt = 0; kt < 8; ++kt) {
          if (kt < 7) cpwait<1>(); else cpwait<0>();
          __syncthreads();  // tile kt landed; fences h0 on kt==0
          if (kt < 6) {
            const float* src = g_w1t + (kt+2)*8192;
            float* dst = w1b + ((kt+2)%3)*8192;
#pragma unroll
            for (int q = 0; q < 4; ++q) {
              int e = (q*THREADS + tid) * 4;
              cp16(dst + e, src + e);
            }
            cpcommit();
          }
          const float* wb = w1b + (kt%3)*8192;
          const int kb = kt*32;
#pragma unroll
          for (int kk = 0; kk < 32; kk += 4) {
            float4 av[2]; ulonglong2 wv[4];
#pragma unroll
            for (int i=0;i<2;i++) av[i] = *(const float4*)(h0 + (r0+i)*LD_H + kb + kk);
#pragma unroll
            for (int t=0;t<4;t++) wv[t] = *(const ulonglong2*)(wb + (kk+t)*256 + c0);
#pragma unroll
            for (int t=0;t<4;t++)
#pragma unroll
              for (int i=0;i<2;i++) {
                u64 ad = dup2(f4get(av[i], t));
                ffma2(a1[i][0], ad, wv[t].x);
                ffma2(a1[i][1], ad, wv[t].y);
              }
          }
        }
#pragma unroll
        for (int i=0;i<2;i++) {
          float2 u0 = unpk(a1[i][0]), u1 = unpk(a1[i][1]);
          float4 o4;
          o4.x = softplusf(u0.x); o4.y = softplusf(u0.y);
          o4.z = softplusf(u1.x); o4.w = softplusf(u1.y);
          *(float4*)(h1 + (r0+i)*LD_H + c0) = o4;
        }
        __syncthreads();

        // layer 2: 1 output/thread, 4 split accumulators (u64) for ILP
        {
          u64 s0 = 0ULL, s1 = 0ULL, s2 = 0ULL, s3 = 0ULL;
#pragma unroll 4
          for (int kk = 0; kk < 256; kk += 8) {
            ulonglong2 wv0 = *(const ulonglong2*)(w2s + d2*LD_W2 + kk);
            ulonglong2 wv1 = *(const ulonglong2*)(w2s + d2*LD_W2 + kk + 4);
            ulonglong2 ua0 = *(const ulonglong2*)(h1 + rr*LD_H + kk);
            ulonglong2 ua1 = *(const ulonglong2*)(h1 + rr*LD_H + kk + 4);
            ffma2(s0, ua0.x, wv0.x); ffma2(s1, ua0.y, wv0.y);
            ffma2(s2, ua1.x, wv1.x); ffma2(s3, ua1.y, wv1.y);
          }
          float2 f0 = unpk(s0), f1 = unpk(s1), f2 = unpk(s2), f3 = unpk(s3);
          ksm[st*512 + rr*32 + d2] =
            ((f0.x + f0.y) + (f1.x + f1.y)) + ((f2.x + f2.y) + (f3.x + f3.y)) + b2s[d2];
        }
        __syncthreads();
      } // stages

      // y += h * (B . k); save at end of interval
      {
        float acc = ysm[tid];
#pragma unroll
        for (int j = 0; j < 6; ++j)
          acc = fmaf(h * c_B[j], ksm[j*512 + tid], acc);
        ysm[tid] = acc;
        if (sub == 1)
          out[(size_t)(s+1)*B*32 + rbase*32 + tid] = acc;
      }
      __syncthreads();
    } // sub
  } // intervals
}

extern "C" void kernel_launch(void* const* d_in, const int* in_sizes, int n_in,
                              void* d_out, int out_size) {
  const float* ts = (const float*)d_in[0];
  const float* y0 = (const float*)d_in[1];
  const float* W0 = (const float*)d_in[2];
  const float* b0 = (const float*)d_in[3];
  const float* W1 = (const float*)d_in[4];
  const float* b1 = (const float*)d_in[5];
  const float* W2 = (const float*)d_in[6];
  const float* b2 = (const float*)d_in[7];
  float* out = (float*)d_out;
  int T = in_sizes[0];
  int B = in_sizes[1] / 32;

  w1t_kernel<<<dim3(8, 8), dim3(32, 8)>>>(W1);

  static int smem_set = 0;
  if (!smem_set) {
    cudaFuncSetAttribute(ode_kernel, cudaFuncAttributeMaxDynamicSharedMemorySize, SMEM_BYTES);
    smem_set = 1;
  }
  ode_kernel<<<B / RPB, THREADS, SMEM_BYTES>>>(ts, y0, W0, b0, b1, W2, b2, out, T, B);
}

// round 8
// speedup vs baseline: 1.3811x; 1.3801x over previous
#include <cuda_runtime.h>

#define THREADS 256
#define LD_H 264
#define LD_T 20

#define OFF_W0T 0
#define OFF_W2S 8192
#define OFF_B0  16512
#define OFF_B1  16768
#define OFF_B2  17024
#define OFF_Y   17056
#define OFF_K   17568
#define OFF_ZT  20640
#define OFF_H0T 21280
#define OFF_H1  26400
#define OFF_W1B 30624
#define SMEM_BYTES ((30624 + 3 * 8192) * 4)

typedef unsigned long long u64;

__constant__ float c_A[6][5] = {
  {0.f,0.f,0.f,0.f,0.f},
  {0.161f,0.f,0.f,0.f,0.f},
  {-0.008480655492356989f,0.335480655492357f,0.f,0.f,0.f},
  {2.8971530571054935f,-6.359448489975075f,4.3622954328695815f,0.f,0.f},
  {5.325864828439257f,-11.748883564062828f,7.4955393428898365f,-0.09249506636175525f,0.f},
  {5.86145544294642f,-12.92096931784711f,8.159367898576159f,-0.071584973281401f,-0.028269050394068383f}};
__constant__ float c_B[6] = {
  0.09646076681806523f,0.01f,0.4798896504144996f,
  1.379008574103742f,-3.290069515436081f,2.324710524099774f};

__device__ float g_w1t[256 * 256]; // g_w1t[k*256+o] = W1[o*256+k]

__device__ __forceinline__ void cp16(float* dst, const float* src) {
  unsigned d = (unsigned)__cvta_generic_to_shared(dst);
  asm volatile("cp.async.ca.shared.global [%0], [%1], 16;" :: "r"(d), "l"(src));
}
__device__ __forceinline__ void cpcommit(){ asm volatile("cp.async.commit_group;"); }
template<int N> __device__ __forceinline__ void cpwait(){ asm volatile("cp.async.wait_group %0;"::"n"(N)); }

__device__ __forceinline__ u64 dup2(float a) {
  u64 r; asm("mov.b64 %0, {%1, %1};" : "=l"(r) : "f"(a)); return r;
}
__device__ __forceinline__ float2 unpk(u64 v) {
  float2 r; asm("mov.b64 {%0, %1}, %2;" : "=f"(r.x), "=f"(r.y) : "l"(v)); return r;
}
__device__ __forceinline__ void ffma2(u64& acc, u64 a, u64 b) {
  asm("fma.rn.f32x2 %0, %1, %2, %0;" : "+l"(acc) : "l"(a), "l"(b));
}

// MUFU softplus
__device__ __forceinline__ float softplusf(float x) {
  float e, l;
  asm("ex2.approx.f32 %0, %1;" : "=f"(e) : "f"(x * 1.4426950408889634f));
  asm("lg2.approx.f32 %0, %1;" : "=f"(l) : "f"(1.0f + e));
  float r = l * 0.69314718055994531f;
  return (x > 15.0f) ? x : r;
}

__global__ void w1t_kernel(const float* __restrict__ W1) {
  __shared__ float tile[32][33];
  int k = blockIdx.x * 32 + threadIdx.x;
#pragma unroll
  for (int j = 0; j < 32; j += 8) {
    int o = blockIdx.y * 32 + threadIdx.y + j;
    tile[threadIdx.y + j][threadIdx.x] = W1[o * 256 + k];
  }
  __syncthreads();
  int o2 = blockIdx.y * 32 + threadIdx.x;
#pragma unroll
  for (int j = 0; j < 32; j += 8) {
    int k2 = blockIdx.x * 32 + threadIdx.y + j;
    g_w1t[k2 * 256 + o2] = tile[threadIdx.x][threadIdx.y + j];
  }
}

__global__ void __launch_bounds__(THREADS, 1)
ode_kernel(const float* __restrict__ ts, const float* __restrict__ y0,
           const float* __restrict__ W0, const float* __restrict__ b0,
           const float* __restrict__ b1, const float* __restrict__ W2,
           const float* __restrict__ b2, float* __restrict__ out, int T, int B) {
  extern __shared__ float sm[];
  float *w0t=sm+OFF_W0T, *w2s=sm+OFF_W2S, *b0s=sm+OFF_B0, *b1s=sm+OFF_B1,
        *b2s=sm+OFF_B2, *ysm=sm+OFF_Y, *ksm=sm+OFF_K, *zt=sm+OFF_ZT,
        *h0t=sm+OFF_H0T, *h1=sm+OFF_H1, *w1b=sm+OFF_W1B;
  const int tid = threadIdx.x;
  const int rbase = blockIdx.x * 16;

  for (int idx = tid; idx < 256*32; idx += THREADS) {
    int o = idx >> 5, k = idx & 31;
    w0t[k*256 + o] = W0[idx];
  }
  for (int idx = tid; idx < 32*256; idx += THREADS) {
    int d = idx >> 8, k = idx & 255;
    w2s[d*260 + k] = W2[idx];
  }
  for (int i = tid; i < 256; i += THREADS) { b0s[i]=b0[i]; b1s[i]=b1[i]; }
  if (tid < 32) b2s[tid] = b2[tid];
  for (int idx = tid; idx < 512; idx += THREADS) {
    float v = y0[rbase*32 + idx];
    ysm[idx] = v;
    out[rbase*32 + idx] = v;
  }
  __syncthreads();

  // layers 0/1: 8 rows x 2 cols per thread; rows packed in f32x2
  const int cg = tid & 127, rg = tid >> 7;
  const int c0 = cg*2, r0 = rg*8;
  // layer 2: 2 rows x 1 col per thread
  const int d2 = tid & 31, rr = (tid >> 5) * 2;

  for (int s = 0; s < T-1; ++s) {
    const float h = (ts[s+1] - ts[s]) * 0.5f;  // NSUB=2
    for (int sub = 0; sub < 2; ++sub) {
      for (int st = 0; st < 6; ++st) {
        // prefetch W1 tiles 0,1
#pragma unroll
        for (int q = 0; q < 8; ++q) {
          int e = (q*THREADS + tid) * 4;
          cp16(w1b + e, g_w1t + e);
        }
        cpcommit();
#pragma unroll
        for (int q = 0; q < 8; ++q) {
          int e = (q*THREADS + tid) * 4;
          cp16(w1b + 8192 + e, g_w1t + 8192 + e);
        }
        cpcommit();

        // z = y + h*sum A[st][j] k_j, stored k-major: zt[d*LD_T + row]
#pragma unroll
        for (int q = 0; q < 2; ++q) {
          int idx = q*THREADS + tid;
          float acc = ysm[idx];
          for (int j = 0; j < st; ++j)
            acc = fmaf(h * c_A[st][j], ksm[j*512 + idx], acc);
          zt[(idx & 31)*LD_T + (idx >> 5)] = acc;
        }
        __syncthreads();

        // layer 0: K=32, rows packed, weight dup'd
        u64 a0[4][2];
        {
          u64 bx = dup2(b0s[c0]), by = dup2(b0s[c0+1]);
#pragma unroll
          for (int p=0;p<4;p++) { a0[p][0]=bx; a0[p][1]=by; }
        }
#pragma unroll
        for (int k = 0; k < 32; ++k) {
          ulonglong2 avA = *(const ulonglong2*)(zt + k*LD_T + r0);
          ulonglong2 avB = *(const ulonglong2*)(zt + k*LD_T + r0 + 4);
          float2 w = *(const float2*)(w0t + k*256 + c0);
          u64 wx = dup2(w.x), wy = dup2(w.y);
          ffma2(a0[0][0], avA.x, wx); ffma2(a0[1][0], avA.y, wx);
          ffma2(a0[2][0], avB.x, wx); ffma2(a0[3][0], avB.y, wx);
          ffma2(a0[0][1], avA.x, wy); ffma2(a0[1][1], avA.y, wy);
          ffma2(a0[2][1], avB.x, wy); ffma2(a0[3][1], avB.y, wy);
        }
        // h0 stored k-major: h0t[col*LD_T + row]
#pragma unroll
        for (int j=0;j<2;j++)
#pragma unroll
          for (int p=0;p<4;p++) {
            float2 u = unpk(a0[p][j]);
            float2 v; v.x = softplusf(u.x); v.y = softplusf(u.y);
            *(float2*)(h0t + (c0+j)*LD_T + r0 + 2*p) = v;
          }

        // layer 1: K=256, triple-buffered W1 stream
        u64 a1[4][2];
        {
          u64 bx = dup2(b1s[c0]), by = dup2(b1s[c0+1]);
#pragma unroll
          for (int p=0;p<4;p++) { a1[p][0]=bx; a1[p][1]=by; }
        }
        for (int kt = 0; kt < 8; ++kt) {
          if (kt < 7) cpwait<1>(); else cpwait<0>();
          __syncthreads();  // tile kt landed; fences h0t on kt==0
          if (kt < 6) {
            const float* src = g_w1t + (kt+2)*8192;
            float* dst = w1b + ((kt+2)%3)*8192;
#pragma unroll
            for (int q = 0; q < 8; ++q) {
              int e = (q*THREADS + tid) * 4;
              cp16(dst + e, src + e);
            }
            cpcommit();
          }
          const float* wb = w1b + (kt%3)*8192;
          const int kb = kt*32;
#pragma unroll
          for (int k2 = 0; k2 < 32; ++k2) {
            ulonglong2 avA = *(const ulonglong2*)(h0t + (kb+k2)*LD_T + r0);
            ulonglong2 avB = *(const ulonglong2*)(h0t + (kb+k2)*LD_T + r0 + 4);
            float2 w = *(const float2*)(wb + k2*256 + c0);
            u64 wx = dup2(w.x), wy = dup2(w.y);
            ffma2(a1[0][0], avA.x, wx); ffma2(a1[1][0], avA.y, wx);
            ffma2(a1[2][0], avB.x, wx); ffma2(a1[3][0], avB.y, wx);
            ffma2(a1[0][1], avA.x, wy); ffma2(a1[1][1], avA.y, wy);
            ffma2(a1[2][1], avB.x, wy); ffma2(a1[3][1], avB.y, wy);
          }
        }
        // h1 row-major for layer 2
#pragma unroll
        for (int j=0;j<2;j++)
#pragma unroll
          for (int p=0;p<4;p++) {
            float2 u = unpk(a1[p][j]);
            h1[(r0+2*p)*LD_H + c0+j]   = softplusf(u.x);
            h1[(r0+2*p+1)*LD_H + c0+j] = softplusf(u.y);
          }
        __syncthreads();

        // layer 2: k_st = h1 @ W2^T + b2
        u64 sa = 0ULL, sb = 0ULL;
#pragma unroll 8
        for (int kk = 0; kk < 256; kk += 4) {
          ulonglong2 wv = *(const ulonglong2*)(w2s + d2*260 + kk);
          ulonglong2 ua = *(const ulonglong2*)(h1 + rr*LD_H + kk);
          ulonglong2 ub = *(const ulonglong2*)(h1 + (rr+1)*LD_H + kk);
          ffma2(sa, ua.x, wv.x); ffma2(sa, ua.y, wv.y);
          ffma2(sb, ub.x, wv.x); ffma2(sb, ub.y, wv.y);
        }
        {
          float2 fa = unpk(sa), fb = unpk(sb);
          ksm[st*512 + rr*32 + d2]     = fa.x + fa.y + b2s[d2];
          ksm[st*512 + (rr+1)*32 + d2] = fb.x + fb.y + b2s[d2];
        }
        __syncthreads();
      } // stages

      // y += h * (B . k); save at end of interval
      {
        u64 acc = *(const u64*)(ysm + tid*2);
#pragma unroll
        for (int j = 0; j < 6; ++j)
          ffma2(acc, dup2(h * c_B[j]), *(const u64*)(ksm + j*512 + tid*2));
        *(u64*)(ysm + tid*2) = acc;
        if (sub == 1)
          *(u64*)(out + (size_t)(s+1)*B*32 + rbase*32 + tid*2) = acc;
      }
      __syncthreads();
    } // sub
  } // intervals
}

extern "C" void kernel_launch(void* const* d_in, const int* in_sizes, int n_in,
                              void* d_out, int out_size) {
  const float* ts = (const float*)d_in[0];
  const float* y0 = (const float*)d_in[1];
  const float* W0 = (const float*)d_in[2];
  const float* b0 = (const float*)d_in[3];
  const float* W1 = (const float*)d_in[4];
  const float* b1 = (const float*)d_in[5];
  const float* W2 = (const float*)d_in[6];
  const float* b2 = (const float*)d_in[7];
  float* out = (float*)d_out;
  int T = in_sizes[0];
  int B = in_sizes[1] / 32;

  w1t_kernel<<<dim3(8, 8), dim3(32, 8)>>>(W1);

  static int smem_set = 0;
  if (!smem_set) {
    cudaFuncSetAttribute(ode_kernel, cudaFuncAttributeMaxDynamicSharedMemorySize, SMEM_BYTES);
    smem_set = 1;
  }
  ode_kernel<<<B / 16, THREADS, SMEM_BYTES>>>(ts, y0, W0, b0, b1, W2, b2, out, T, B);
}

// round 9
// speedup vs baseline: 1.3838x; 1.0020x over previous
#include <cuda_runtime.h>

#define THREADS 256
#define LD_H 264
#define LD_T 20

#define OFF_W0T 0
#define OFF_W2S 8192
#define OFF_B0  16512
#define OFF_B1  16768
#define OFF_B2  17024
#define OFF_Y   17056
#define OFF_K   17568
#define OFF_ZT  20640
#define OFF_H0T 21280
#define OFF_H1  26400
#define OFF_W1B 30624
#define SMEM_BYTES ((30624 + 3 * 8192) * 4)

typedef unsigned long long u64;

__constant__ float c_A[6][5] = {
  {0.f,0.f,0.f,0.f,0.f},
  {0.161f,0.f,0.f,0.f,0.f},
  {-0.008480655492356989f,0.335480655492357f,0.f,0.f,0.f},
  {2.8971530571054935f,-6.359448489975075f,4.3622954328695815f,0.f,0.f},
  {5.325864828439257f,-11.748883564062828f,7.4955393428898365f,-0.09249506636175525f,0.f},
  {5.86145544294642f,-12.92096931784711f,8.159367898576159f,-0.071584973281401f,-0.028269050394068383f}};
__constant__ float c_B[6] = {
  0.09646076681806523f,0.01f,0.4798896504144996f,
  1.379008574103742f,-3.290069515436081f,2.324710524099774f};

__device__ float g_w1t[256 * 256]; // g_w1t[k*256+o] = W1[o*256+k]

__device__ __forceinline__ void cp16(float* dst, const float* src) {
  unsigned d = (unsigned)__cvta_generic_to_shared(dst);
  asm volatile("cp.async.ca.shared.global [%0], [%1], 16;" :: "r"(d), "l"(src));
}
__device__ __forceinline__ void cpcommit(){ asm volatile("cp.async.commit_group;"); }
template<int N> __device__ __forceinline__ void cpwait(){ asm volatile("cp.async.wait_group %0;"::"n"(N)); }

__device__ __forceinline__ u64 dup2(float a) {
  u64 r; asm("mov.b64 %0, {%1, %1};" : "=l"(r) : "f"(a)); return r;
}
__device__ __forceinline__ float2 unpk(u64 v) {
  float2 r; asm("mov.b64 {%0, %1}, %2;" : "=f"(r.x), "=f"(r.y) : "l"(v)); return r;
}
__device__ __forceinline__ void ffma2(u64& acc, u64 a, u64 b) {
  asm("fma.rn.f32x2 %0, %1, %2, %0;" : "+l"(acc) : "l"(a), "l"(b));
}

// MUFU softplus
__device__ __forceinline__ float softplusf(float x) {
  float e, l;
  asm("ex2.approx.f32 %0, %1;" : "=f"(e) : "f"(x * 1.4426950408889634f));
  asm("lg2.approx.f32 %0, %1;" : "=f"(l) : "f"(1.0f + e));
  float r = l * 0.69314718055994531f;
  return (x > 15.0f) ? x : r;
}

__global__ void w1t_kernel(const float* __restrict__ W1) {
  __shared__ float tile[32][33];
  int k = blockIdx.x * 32 + threadIdx.x;
#pragma unroll
  for (int j = 0; j < 32; j += 8) {
    int o = blockIdx.y * 32 + threadIdx.y + j;
    tile[threadIdx.y + j][threadIdx.x] = W1[o * 256 + k];
  }
  __syncthreads();
  int o2 = blockIdx.y * 32 + threadIdx.x;
#pragma unroll
  for (int j = 0; j < 32; j += 8) {
    int k2 = blockIdx.x * 32 + threadIdx.y + j;
    g_w1t[k2 * 256 + o2] = tile[threadIdx.x][threadIdx.y + j];
  }
}

__global__ void __launch_bounds__(THREADS, 1)
ode_kernel(const float* __restrict__ ts, const float* __restrict__ y0,
           const float* __restrict__ W0, const float* __restrict__ b0,
           const float* __restrict__ b1, const float* __restrict__ W2,
           const float* __restrict__ b2, float* __restrict__ out, int T, int B) {
  extern __shared__ float sm[];
  float *w0t=sm+OFF_W0T, *w2s=sm+OFF_W2S, *b0s=sm+OFF_B0, *b1s=sm+OFF_B1,
        *b2s=sm+OFF_B2, *ysm=sm+OFF_Y, *ksm=sm+OFF_K, *zt=sm+OFF_ZT,
        *h0t=sm+OFF_H0T, *h1=sm+OFF_H1, *w1b=sm+OFF_W1B;
  const int tid = threadIdx.x;
  const int rbase = blockIdx.x * 16;

  for (int idx = tid; idx < 256*32; idx += THREADS) {
    int o = idx >> 5, k = idx & 31;
    w0t[k*256 + o] = W0[idx];
  }
  for (int idx = tid; idx < 32*256; idx += THREADS) {
    int d = idx >> 8, k = idx & 255;
    w2s[d*260 + k] = W2[idx];
  }
  for (int i = tid; i < 256; i += THREADS) { b0s[i]=b0[i]; b1s[i]=b1[i]; }
  if (tid < 32) b2s[tid] = b2[tid];
  for (int idx = tid; idx < 512; idx += THREADS) {
    float v = y0[rbase*32 + idx];
    ysm[idx] = v;
    out[rbase*32 + idx] = v;
  }
  __syncthreads();

  // layers 0/1: 8 rows x 2 cols per thread; rows packed in f32x2
  const int cg = tid & 127, rg = tid >> 7;
  const int c0 = cg*2, r0 = rg*8;
  // layer 2: 2 rows x 1 col per thread
  const int d2 = tid & 31, rr = (tid >> 5) * 2;

  for (int s = 0; s < T-1; ++s) {
    const float h = (ts[s+1] - ts[s]) * 0.5f;  // NSUB=2
    for (int sub = 0; sub < 2; ++sub) {
      for (int st = 0; st < 6; ++st) {
        // prefetch W1 tiles 0,1
#pragma unroll
        for (int q = 0; q < 8; ++q) {
          int e = (q*THREADS + tid) * 4;
          cp16(w1b + e, g_w1t + e);
        }
        cpcommit();
#pragma unroll
        for (int q = 0; q < 8; ++q) {
          int e = (q*THREADS + tid) * 4;
          cp16(w1b + 8192 + e, g_w1t + 8192 + e);
        }
        cpcommit();

        // z = y + h*sum A[st][j] k_j, stored k-major: zt[d*LD_T + row]
#pragma unroll
        for (int q = 0; q < 2; ++q) {
          int idx = q*THREADS + tid;
          float acc = ysm[idx];
          for (int j = 0; j < st; ++j)
            acc = fmaf(h * c_A[st][j], ksm[j*512 + idx], acc);
          zt[(idx & 31)*LD_T + (idx >> 5)] = acc;
        }
        __syncthreads();

        // layer 0: K=32, rows packed, weight dup'd
        u64 a0[4][2];
        {
          u64 bx = dup2(b0s[c0]), by = dup2(b0s[c0+1]);
#pragma unroll
          for (int p=0;p<4;p++) { a0[p][0]=bx; a0[p][1]=by; }
        }
#pragma unroll
        for (int k = 0; k < 32; ++k) {
          ulonglong2 avA = *(const ulonglong2*)(zt + k*LD_T + r0);
          ulonglong2 avB = *(const ulonglong2*)(zt + k*LD_T + r0 + 4);
          float2 w = *(const float2*)(w0t + k*256 + c0);
          u64 wx = dup2(w.x), wy = dup2(w.y);
          ffma2(a0[0][0], avA.x, wx); ffma2(a0[1][0], avA.y, wx);
          ffma2(a0[2][0], avB.x, wx); ffma2(a0[3][0], avB.y, wx);
          ffma2(a0[0][1], avA.x, wy); ffma2(a0[1][1], avA.y, wy);
          ffma2(a0[2][1], avB.x, wy); ffma2(a0[3][1], avB.y, wy);
        }
        // h0 stored k-major: h0t[col*LD_T + row]
#pragma unroll
        for (int j=0;j<2;j++)
#pragma unroll
          for (int p=0;p<4;p++) {
            float2 u = unpk(a0[p][j]);
            float2 v; v.x = softplusf(u.x); v.y = softplusf(u.y);
            *(float2*)(h0t + (c0+j)*LD_T + r0 + 2*p) = v;
          }

        // layer 1: K=256, triple-buffered W1 stream
        u64 a1[4][2];
        {
          u64 bx = dup2(b1s[c0]), by = dup2(b1s[c0+1]);
#pragma unroll
          for (int p=0;p<4;p++) { a1[p][0]=bx; a1[p][1]=by; }
        }
        for (int kt = 0; kt < 8; ++kt) {
          if (kt < 7) cpwait<1>(); else cpwait<0>();
          __syncthreads();  // tile kt landed; fences h0t on kt==0
          if (kt < 6) {
            const float* src = g_w1t + (kt+2)*8192;
            float* dst = w1b + ((kt+2)%3)*8192;
#pragma unroll
            for (int q = 0; q < 8; ++q) {
              int e = (q*THREADS + tid) * 4;
              cp16(dst + e, src + e);
            }
            cpcommit();
          }
          const float* wb = w1b + (kt%3)*8192;
          const int kb = kt*32;
#pragma unroll
          for (int k2 = 0; k2 < 32; ++k2) {
            ulonglong2 avA = *(const ulonglong2*)(h0t + (kb+k2)*LD_T + r0);
            ulonglong2 avB = *(const ulonglong2*)(h0t + (kb+k2)*LD_T + r0 + 4);
            float2 w = *(const float2*)(wb + k2*256 + c0);
            u64 wx = dup2(w.x), wy = dup2(w.y);
            ffma2(a1[0][0], avA.x, wx); ffma2(a1[1][0], avA.y, wx);
            ffma2(a1[2][0], avB.x, wx); ffma2(a1[3][0], avB.y, wx);
            ffma2(a1[0][1], avA.x, wy); ffma2(a1[1][1], avA.y, wy);
            ffma2(a1[2][1], avB.x, wy); ffma2(a1[3][1], avB.y, wy);
          }
        }
        // h1 row-major for layer 2
#pragma unroll
        for (int j=0;j<2;j++)
#pragma unroll
          for (int p=0;p<4;p++) {
            float2 u = unpk(a1[p][j]);
            h1[(r0+2*p)*LD_H + c0+j]   = softplusf(u.x);
            h1[(r0+2*p+1)*LD_H + c0+j] = softplusf(u.y);
          }
        __syncthreads();

        // layer 2: k_st = h1 @ W2^T + b2
        u64 sa = 0ULL, sb = 0ULL;
#pragma unroll 8
        for (int kk = 0; kk < 256; kk += 4) {
          ulonglong2 wv = *(const ulonglong2*)(w2s + d2*260 + kk);
          ulonglong2 ua = *(const ulonglong2*)(h1 + rr*LD_H + kk);
          ulonglong2 ub = *(const ulonglong2*)(h1 + (rr+1)*LD_H + kk);
          ffma2(sa, ua.x, wv.x); ffma2(sa, ua.y, wv.y);
          ffma2(sb, ub.x, wv.x); ffma2(sb, ub.y, wv.y);
        }
        {
          float2 fa = unpk(sa), fb = unpk(sb);
          ksm[st*512 + rr*32 + d2]     = fa.x + fa.y + b2s[d2];
          ksm[st*512 + (rr+1)*32 + d2] = fb.x + fb.y + b2s[d2];
        }
        __syncthreads();
      } // stages

      // y += h * (B . k); save at end of interval
      {
        u64 acc = *(const u64*)(ysm + tid*2);
#pragma unroll
        for (int j = 0; j < 6; ++j)
          ffma2(acc, dup2(h * c_B[j]), *(const u64*)(ksm + j*512 + tid*2));
        *(u64*)(ysm + tid*2) = acc;
        if (sub == 1)
          *(u64*)(out + (size_t)(s+1)*B*32 + rbase*32 + tid*2) = acc;
      }
      __syncthreads();
    } // sub
  } // intervals
}

extern "C" void kernel_launch(void* const* d_in, const int* in_sizes, int n_in,
                              void* d_out, int out_size) {
  const float* ts = (const float*)d_in[0];
  const float* y0 = (const float*)d_in[1];
  const float* W0 = (const float*)d_in[2];
  const float* b0 = (const float*)d_in[3];
  const float* W1 = (const float*)d_in[4];
  const float* b1 = (const float*)d_in[5];
  const float* W2 = (const float*)d_in[6];
  const float* b2 = (const float*)d_in[7];
  float* out = (float*)d_out;
  int T = in_sizes[0];
  int B = in_sizes[1] / 32;

  w1t_kernel<<<dim3(8, 8), dim3(32, 8)>>>(W1);

  static int smem_set = 0;
  if (!smem_set) {
    cudaFuncSetAttribute(ode_kernel, cudaFuncAttributeMaxDynamicSharedMemorySize, SMEM_BYTES);
    smem_set = 1;
  }
  ode_kernel<<<B / 16, THREADS, SMEM_BYTES>>>(ts, y0, W0, b0, b1, W2, b2, out, T, B);
}